// round 2
// baseline (speedup 1.0000x reference)
#include <cuda_runtime.h>

// Entropy_70136815944310 — local-window KDE entropy.  (Re-land of round-0
// kernel: round-1 failure was a GB300 broker/container error; kernel never ran.)
//
// x: [8,3,96,96] fp32 in [0,255]; out: [8,3,96,96] fp32.
//
// Key insight: KDE kernel k(x,b) = sig(10(x-b))*(1-sig(10(x-b))) = e/(1+e)^2
// with e = exp(-10|x-b|). Decays by e^-10 per bin of distance -> only bins
// floor(x)-1 .. floor(x)+2 matter (truncation error ~1e-7 in entropy; the
// fp32 reference itself flushes 1-sigmoid to 0 beyond |d|~17).
//
// Entropy per pixel: H = (S*log(S') - sum q*log q) / S', S' = S + 1e-10.

#define IMG       96
#define TILE_W    16
#define TILE_H    12
#define THREADS   (TILE_W * TILE_H)   // 192
#define HALO      2
#define IN_W      (TILE_W + 2 * HALO) // 20
#define IN_H      (TILE_H + 2 * HALO) // 16
#define NBINS     256
#define HSTRIDE   260                 // 256 + 4 pad: bank = (4*tid + b) % 32, conflict-free
#define SMEM_BYTES ((THREADS * HSTRIDE + IN_H * IN_W) * 4)

__global__ __launch_bounds__(THREADS, 1)
void entropy_kernel(const float* __restrict__ in, float* __restrict__ out, int planes) {
    extern __shared__ float smem[];
    float* hist = smem;
    float* tile = smem + THREADS * HSTRIDE;

    const int tid   = threadIdx.x;
    const int plane = blockIdx.y;
    const int tIdx  = blockIdx.x;                      // 0..47
    const int tx0   = (tIdx % (IMG / TILE_W)) * TILE_W;
    const int ty0   = (tIdx / (IMG / TILE_W)) * TILE_H;
    const float* img = in + (size_t)plane * IMG * IMG;

    // ---- load input tile with halo; OOB -> sentinel -10 (its 4 bins land <0,
    // skipped by the bounds test, matching SAME padding's additive identity) ----
    for (int idx = tid; idx < IN_H * IN_W; idx += THREADS) {
        int r = idx / IN_W, c = idx % IN_W;
        int gy = ty0 + r - HALO, gx = tx0 + c - HALO;
        float v = -10.0f;
        if ((unsigned)gy < (unsigned)IMG && (unsigned)gx < (unsigned)IMG)
            v = img[gy * IMG + gx];
        tile[idx] = v;
    }

    // ---- zero own histogram (float4: tid*260 words = 1040 B, 16B-aligned) ----
    float* h = hist + tid * HSTRIDE;
    float4* h4 = (float4*)h;
    #pragma unroll 8
    for (int i = 0; i < NBINS / 4; i++)
        h4[i] = make_float4(0.f, 0.f, 0.f, 0.f);

    __syncthreads();

    const int ox = tid % TILE_W;
    const int oy = tid / TILE_W;

    // ---- accumulate sparse KDE mass over the 5x5 window ----
    for (int dy = 0; dy < 5; dy++) {
        const float* trow = tile + (oy + dy) * IN_W + ox;
        #pragma unroll
        for (int dx = 0; dx < 5; dx++) {
            float x = trow[dx];
            int i0 = (int)floorf(x);
            #pragma unroll
            for (int j = -1; j <= 2; j++) {
                int b = i0 + j;
                if ((unsigned)b < 256u) {
                    float t = x - (float)b;
                    float e = __expf(-10.0f * fabsf(t));   // e^{-10|t|}
                    float u = 1.0f + e;
                    float k = __fdividef(e, u * u);        // sig*(1-sig)
                    h[b] += k;
                }
            }
        }
    }
    // own-thread histogram: no sync needed before readback

    // ---- scan: S = sum q, T2 = sum q*log q ----
    float S = 0.f, T2 = 0.f;
    #pragma unroll 4
    for (int i = 0; i < NBINS / 4; i++) {
        float4 q = h4[i];
        S += (q.x + q.y) + (q.z + q.w);
        // q==0 -> 0 * log(1e-37) == 0 exactly; q>0 -> fmaxf is identity
        T2 += q.x * __logf(fmaxf(q.x, 1e-37f));
        T2 += q.y * __logf(fmaxf(q.y, 1e-37f));
        T2 += q.z * __logf(fmaxf(q.z, 1e-37f));
        T2 += q.w * __logf(fmaxf(q.w, 1e-37f));
    }

    float Sp = S + 1e-10f;
    float H  = __fdividef(S * __logf(Sp) - T2, Sp);

    out[(size_t)plane * IMG * IMG + (ty0 + oy) * IMG + (tx0 + ox)] = H;
}

extern "C" void kernel_launch(void* const* d_in, const int* in_sizes, int n_in,
                              void* d_out, int out_size) {
    const float* x = (const float*)d_in[0];
    float* out = (float*)d_out;

    int planes = in_sizes[0] / (IMG * IMG);   // 8*3 = 24

    cudaFuncSetAttribute(entropy_kernel,
                         cudaFuncAttributeMaxDynamicSharedMemorySize, SMEM_BYTES);

    dim3 grid((IMG / TILE_W) * (IMG / TILE_H), planes);  // (48, 24)
    entropy_kernel<<<grid, THREADS, SMEM_BYTES>>>(x, out, planes);
}

// round 3
// speedup vs baseline: 1.4042x; 1.4042x over previous
#include <cuda_runtime.h>

// Entropy_70136815944310 — local-window KDE entropy, R3: 4-pass bin-split
// histogram for 4x occupancy (272B/thread hist vs 1040B -> 4 CTAs/SM).
//
// x: [8,3,96,96] fp32 in [0,255]; out: [8,3,96,96] fp32.
//
// KDE kernel k(x,b) = e/(1+e)^2, e = exp(-10|x-b|): only bins
// floor(x)-1..floor(x)+2 matter (>=1e-7 accuracy, validated rel_err 3.4e-7).
// With f = x-floor(x), the 4 bins' e-values are gE, E, g/E, g^2/E where
// E = exp(-10f), g = exp(-10): 1 ex2 + 3 rcp per value instead of 4 exp+div.
// Far bins (e <= 4.54e-5): k = e(1-2e), abs err < 3e-13.
//
// H = (S*log(S') - sum q*log q) / S', S' = S + 1e-10.

#define IMG       96
#define TILE_W    16
#define TILE_H    12
#define THREADS   (TILE_W * TILE_H)   // 192
#define HALO      2
#define IN_W      (TILE_W + 2 * HALO) // 20
#define IN_H      (TILE_H + 2 * HALO) // 16
#define NPASS     4
#define PBINS     64                  // bins per pass
#define HSTRIDE   68                  // 64 + 4 pad; 272B: 16B-aligned, scan conflict-free
#define SMEM_BYTES ((THREADS * HSTRIDE + IN_H * IN_W) * 4)   // 53,504 B

__device__ __forceinline__ float frcp(float x) {
    float r; asm("rcp.approx.f32 %0, %1;" : "=f"(r) : "f"(x)); return r;
}

__global__ __launch_bounds__(THREADS, 4)
void entropy_kernel(const float* __restrict__ in, float* __restrict__ out) {
    extern __shared__ float smem[];
    float* tile = smem + THREADS * HSTRIDE;

    const int tid   = threadIdx.x;
    const int plane = blockIdx.y;
    const int tIdx  = blockIdx.x;                      // 0..47
    const int tx0   = (tIdx % (IMG / TILE_W)) * TILE_W;
    const int ty0   = (tIdx / (IMG / TILE_W)) * TILE_H;
    const float* img = in + (size_t)plane * IMG * IMG;

    // ---- input tile + halo; OOB -> sentinel -10 (bins <0 in every pass,
    // rejected by range check == SAME padding's additive identity) ----
    for (int idx = tid; idx < IN_H * IN_W; idx += THREADS) {
        int r = idx / IN_W, c = idx % IN_W;
        int gy = ty0 + r - HALO, gx = tx0 + c - HALO;
        float val = -10.0f;
        if ((unsigned)gy < (unsigned)IMG && (unsigned)gx < (unsigned)IMG)
            val = img[gy * IMG + gx];
        tile[idx] = val;
    }

    // ---- zero own 64-bin histogram ----
    float* h = smem + tid * HSTRIDE;
    float4* h4 = (float4*)h;
    #pragma unroll
    for (int i = 0; i < PBINS / 4; i++)
        h4[i] = make_float4(0.f, 0.f, 0.f, 0.f);

    __syncthreads();

    // ---- 25 window values into registers (reused by all 4 passes) ----
    const int ox = tid % TILE_W;
    const int oy = tid / TILE_W;
    float v[25];
    {
        const float* t0 = tile + oy * IN_W + ox;
        #pragma unroll
        for (int dy = 0; dy < 5; dy++)
            #pragma unroll
            for (int dx = 0; dx < 5; dx++)
                v[dy * 5 + dx] = t0[dy * IN_W + dx];
    }

    const float g  = 4.5399929762484854e-05f;   // exp(-10)
    const float g2 = 2.0611536224385578e-09f;   // exp(-20)
    float S = 0.f, T2 = 0.f;

    #pragma unroll 1   // keep code size down; inner loops fully unrolled
    for (int p = 0; p < NPASS; p++) {
        const int base = p * PBINS;

        // -- accumulate this pass's bin range --
        #pragma unroll
        for (int i = 0; i < 25; i++) {
            float x  = v[i];
            float fl = floorf(x);
            int   u  = (int)fl - base;             // pass-relative center bin
            if ((unsigned)(u + 2) <= 66u) {        // some bin of u-1..u+2 in [0,64)
                float f  = x - fl;                 // [0,1)
                float E  = __expf(-10.f * f);
                float iE = frcp(E);
                float e1 = g * iE;                 // exp(-10(1-f))
                float r0 = frcp(1.f + E);
                float r1 = frcp(1.f + e1);
                float k0 = E  * r0 * r0;           // bin i0   (|t| = f)
                float k1 = e1 * r1 * r1;           // bin i0+1 (|t| = 1-f)
                float em = g  * E;                 // bin i0-1 (|t| = 1+f)
                float km1 = em - 2.f * em * em;
                float e2 = g2 * iE;                // bin i0+2 (|t| = 2-f)
                float k2 = e2 - 2.f * e2 * e2;
                if ((unsigned)(u - 1) < (unsigned)PBINS) h[u - 1] += km1;
                if ((unsigned)(u    ) < (unsigned)PBINS) h[u    ] += k0;
                if ((unsigned)(u + 1) < (unsigned)PBINS) h[u + 1] += k1;
                if ((unsigned)(u + 2) < (unsigned)PBINS) h[u + 2] += k2;
            }
        }

        // -- scan-with-clear: S, sum q*log q; re-zeroed for next pass --
        #pragma unroll
        for (int i = 0; i < PBINS / 4; i++) {
            float4 q = h4[i];
            h4[i] = make_float4(0.f, 0.f, 0.f, 0.f);
            S += (q.x + q.y) + (q.z + q.w);
            // q==0 -> 0 * log(1e-37) == 0 exactly; q>0 -> fmaxf identity
            T2 += q.x * __logf(fmaxf(q.x, 1e-37f));
            T2 += q.y * __logf(fmaxf(q.y, 1e-37f));
            T2 += q.z * __logf(fmaxf(q.z, 1e-37f));
            T2 += q.w * __logf(fmaxf(q.w, 1e-37f));
        }
    }

    float Sp = S + 1e-10f;
    float H  = __fdividef(S * __logf(Sp) - T2, Sp);

    out[(size_t)plane * IMG * IMG + (ty0 + oy) * IMG + (tx0 + ox)] = H;
}

extern "C" void kernel_launch(void* const* d_in, const int* in_sizes, int n_in,
                              void* d_out, int out_size) {
    const float* x = (const float*)d_in[0];
    float* out = (float*)d_out;

    cudaFuncSetAttribute(entropy_kernel,
                         cudaFuncAttributeMaxDynamicSharedMemorySize, SMEM_BYTES);

    int planes = in_sizes[0] / (IMG * IMG);              // 24
    dim3 grid((IMG / TILE_W) * (IMG / TILE_H), planes);  // (48, 24)
    entropy_kernel<<<grid, THREADS, SMEM_BYTES>>>(x, out);
}

// round 4
// speedup vs baseline: 2.3927x; 1.7040x over previous
#include <cuda_runtime.h>

// Entropy_70136815944310 — R4: vertical sliding-window KDE entropy.
// x: [8,3,96,96] fp32 in [0,255]; out: same shape fp32.
//
// Each thread owns (plane, column, 8-row segment): builds a 5x5-window
// 256-bin histogram once, then slides down 7 rows (remove 5 / add 5 values),
// incrementally maintaining S = sum q and T2 = sum q*log q.
// H = (S*log(S') - T2)/S', S' = S + 1e-10.
//
// KDE kernel k(x,b) = e/(1+e)^2, e = exp(-10|x-b|): only bins
// floor(x)-1..floor(x)+2 matter (validated: rel_err 3.4e-7). With
// f = x-floor(x): E = exp(-10f); the 4 bins' e are gE, E, g/E, g2/E,
// g = exp(-10). Far bins use k = e(1-2e) (err < 3e-13).

#define IMG      96
#define SEG      8                    // output rows per thread
#define NSEG     (IMG / SEG)          // 12
#define THREADS  IMG                  // 96: thread = column
#define HSTRIDE  260                  // 256 + 4 pad (16B-aligned, scan conflict-free)
#define TROWS    (SEG + 4)            // 12
#define TCOLS    (IMG + 4)            // 100
#define NBINS    256
#define SMEM_BYTES ((THREADS * HSTRIDE + TROWS * TCOLS) * 4)   // 104,640 B

__device__ __forceinline__ float frcp(float v) {
    float r; asm("rcp.approx.f32 %0, %1;" : "=f"(r) : "f"(v)); return r;
}
// q==0 -> 0*log(1e-37)==0 exactly; q<0 (rounding residual ~1e-11) -> ~1e-9, negligible
__device__ __forceinline__ float qlogq(float q) {
    return q * __logf(fmaxf(q, 1e-37f));
}

struct Kset { int i0; float km1, k0, k1, k2; };

__device__ __forceinline__ Kset kde4(float x) {
    const float g  = 4.5399929762484854e-05f;   // exp(-10)
    const float g2 = 2.0611536224385578e-09f;   // exp(-20)
    Kset ks;
    float fl = floorf(x);
    ks.i0 = (int)fl;
    float f  = x - fl;
    float E  = __expf(-10.f * f);
    float iE = frcp(E);
    float e1 = g * iE;
    float r0 = frcp(1.f + E);
    float r1 = frcp(1.f + e1);
    ks.k0 = E  * r0 * r0;              // bin i0
    ks.k1 = e1 * r1 * r1;              // bin i0+1
    float em = g * E;
    ks.km1 = em - 2.f * em * em;       // bin i0-1
    float e2 = g2 * iE;
    ks.k2  = e2 - 2.f * e2 * e2;       // bin i0+2
    return ks;
}

__global__ __launch_bounds__(THREADS, 2)
void entropy_kernel(const float* __restrict__ in, float* __restrict__ out) {
    extern __shared__ float smem[];
    float* tile = smem + THREADS * HSTRIDE;

    const int x     = threadIdx.x;                 // column
    const int plane = blockIdx.y;
    const int r0    = blockIdx.x * SEG;
    const float* img = in  + (size_t)plane * IMG * IMG;
    float*       o   = out + (size_t)plane * IMG * IMG;

    // ---- tile: rows r0-2 .. r0+SEG+1, cols -2..97; OOB -> sentinel -10
    // (its bins are negative -> rejected, matching SAME padding) ----
    for (int idx = x; idx < TROWS * TCOLS; idx += THREADS) {
        int r = idx / TCOLS, c = idx % TCOLS;
        int gy = r0 + r - 2, gx = c - 2;
        float v = -10.0f;
        if ((unsigned)gy < (unsigned)IMG && (unsigned)gx < (unsigned)IMG)
            v = img[gy * IMG + gx];
        tile[idx] = v;
    }

    // ---- zero own 256-bin histogram ----
    float* h  = smem + x * HSTRIDE;
    float4* h4 = (float4*)h;
    #pragma unroll 8
    for (int i = 0; i < NBINS / 4; i++)
        h4[i] = make_float4(0.f, 0.f, 0.f, 0.f);

    __syncthreads();

    // ---- build initial histogram for y = r0 (tile rows 0..4, cols x..x+4) ----
    #pragma unroll 1
    for (int wr = 0; wr < 5; wr++) {
        const float* trow = tile + wr * TCOLS + x;
        #pragma unroll
        for (int wc = 0; wc < 5; wc++) {
            float v = trow[wc];
            if (v >= 0.f) {
                Kset ks = kde4(v);
                if ((unsigned)(ks.i0 - 1) < (unsigned)NBINS) h[ks.i0 - 1] += ks.km1;
                h[ks.i0]     += ks.k0;                    // i0 in [0,254]: always valid
                h[ks.i0 + 1] += ks.k1;                    // i0+1 in [1,255]: always valid
                if ((unsigned)(ks.i0 + 2) < (unsigned)NBINS) h[ks.i0 + 2] += ks.k2;
            }
        }
    }

    // ---- full scan once: S, T2 ----
    float S = 0.f, T2 = 0.f;
    #pragma unroll 4
    for (int i = 0; i < NBINS / 4; i++) {
        float4 q = h4[i];
        S  += (q.x + q.y) + (q.z + q.w);
        T2 += qlogq(q.x) + qlogq(q.y) + qlogq(q.z) + qlogq(q.w);
    }

    {
        float Sp = S + 1e-10f;
        o[r0 * IMG + x] = __fdividef(S * __logf(Sp) - T2, Sp);
    }

    // ---- slide down 7 rows: remove row y-3 (tile row step-1),
    //      add row y+2 (tile row step+4), incremental S/T2 ----
    #pragma unroll 1
    for (int step = 1; step < SEG; step++) {
        const float* rem = tile + (step - 1) * TCOLS + x;
        const float* add = tile + (step + 4) * TCOLS + x;

        #pragma unroll
        for (int wc = 0; wc < 5; wc++) {
            float v = rem[wc];
            if (v >= 0.f) {
                Kset ks = kde4(v);
                #pragma unroll
                for (int j = 0; j < 4; j++) {
                    int   b = ks.i0 - 1 + j;
                    float k = (j == 0) ? ks.km1 : (j == 1) ? ks.k0
                            : (j == 2) ? ks.k1  : ks.k2;
                    if ((unsigned)b < (unsigned)NBINS) {
                        float q  = h[b];
                        float qn = q - k;
                        h[b] = qn;
                        T2  += qlogq(qn) - qlogq(q);
                        S   -= k;
                    }
                }
            }
        }
        #pragma unroll
        for (int wc = 0; wc < 5; wc++) {
            float v = add[wc];
            if (v >= 0.f) {
                Kset ks = kde4(v);
                #pragma unroll
                for (int j = 0; j < 4; j++) {
                    int   b = ks.i0 - 1 + j;
                    float k = (j == 0) ? ks.km1 : (j == 1) ? ks.k0
                            : (j == 2) ? ks.k1  : ks.k2;
                    if ((unsigned)b < (unsigned)NBINS) {
                        float q  = h[b];
                        float qn = q + k;
                        h[b] = qn;
                        T2  += qlogq(qn) - qlogq(q);
                        S   += k;
                    }
                }
            }
        }

        float Sp = S + 1e-10f;
        o[(r0 + step) * IMG + x] = __fdividef(S * __logf(Sp) - T2, Sp);
    }
}

extern "C" void kernel_launch(void* const* d_in, const int* in_sizes, int n_in,
                              void* d_out, int out_size) {
    const float* x = (const float*)d_in[0];
    float* out = (float*)d_out;

    cudaFuncSetAttribute(entropy_kernel,
                         cudaFuncAttributeMaxDynamicSharedMemorySize, SMEM_BYTES);

    int planes = in_sizes[0] / (IMG * IMG);   // 24
    dim3 grid(NSEG, planes);                  // (12, 24) = 288 CTAs
    entropy_kernel<<<grid, THREADS, SMEM_BYTES>>>(x, out);
}

// round 5
// speedup vs baseline: 2.8556x; 1.1935x over previous
#include <cuda_runtime.h>

// Entropy_70136815944310 — R5: vertical sliding window + parity-split thread
// pairs. Two threads per column share one 256-bin histogram: thread parity p
// owns bins with (b&1)==p. Halves each thread's RMW chain, doubles warps/SM
// (12) at unchanged smem. Partial S/T2 per thread, combined via shfl_xor(1).
//
// x: [8,3,96,96] fp32 in [0,255]; out: same shape fp32.
// KDE kernel k(x,b) = e/(1+e)^2, e = exp(-10|x-b|): only bins
// floor(x)-1..floor(x)+2 matter (validated rel_err ~4e-7). With
// f = x-floor(x): E = exp(-10f); bins' e are gE, E, g/E, g2/E, g = exp(-10).
// Far bins: k = e(1-2e), err < 3e-13.
// H = (S*log(S') - T2)/S', S' = S + 1e-10, T2 = sum q*log q.

#define IMG      96
#define SEG      8                    // output rows per thread pair
#define NSEG     (IMG / SEG)          // 12
#define THREADS  (IMG * 2)            // 192: lane pair (2c, 2c+1) = column c
#define HSTRIDE  260                  // 256 + 4 pad
#define TROWS    (SEG + 4)            // 12
#define TCOLS    (IMG + 4)            // 100
#define NBINS    256
#define SMEM_BYTES ((IMG * HSTRIDE + TROWS * TCOLS) * 4)   // 104,640 B

__device__ __forceinline__ float frcp(float v) {
    float r; asm("rcp.approx.f32 %0, %1;" : "=f"(r) : "f"(v)); return r;
}
// q==0 -> 0*log(1e-37)==0 exactly; tiny negative rounding residue -> ~1e-9, negligible
__device__ __forceinline__ float qlogq(float q) {
    return q * __logf(fmaxf(q, 1e-37f));
}

struct Kset { int i0; float km1, k0, k1, k2; };

__device__ __forceinline__ Kset kde4(float x) {
    const float g  = 4.5399929762484854e-05f;   // exp(-10)
    const float g2 = 2.0611536224385578e-09f;   // exp(-20)
    Kset ks;
    float fl = floorf(x);
    ks.i0 = (int)fl;
    float f  = x - fl;
    float E  = __expf(-10.f * f);
    float iE = frcp(E);
    float e1 = g * iE;
    float r0 = frcp(1.f + E);
    float r1 = frcp(1.f + e1);
    ks.k0 = E  * r0 * r0;              // bin i0
    ks.k1 = e1 * r1 * r1;              // bin i0+1
    float em = g * E;
    ks.km1 = em - 2.f * em * em;       // bin i0-1
    float e2 = g2 * iE;
    ks.k2  = e2 - 2.f * e2 * e2;       // bin i0+2
    return ks;
}

// Update the 2 bins of ks that match this thread's parity. sgn = +1 add / -1 rem.
// Bins {i0-1, i0+1} share parity (i0-1)&1; bins {i0, i0+2} share i0&1.
__device__ __forceinline__ void update2(float* h, const Kset& ks, int par,
                                        float sgn, float& S, float& T2) {
    int bA, bB; float kA, kB;
    if ((ks.i0 & 1) == par) { bA = ks.i0;     kA = ks.k0;  bB = ks.i0 + 2; kB = ks.k2; }
    else                    { bA = ks.i0 - 1; kA = ks.km1; bB = ks.i0 + 1; kB = ks.k1; }
    if ((unsigned)bA < (unsigned)NBINS) {
        float q = h[bA], qn = q + sgn * kA;
        h[bA] = qn;  T2 += qlogq(qn) - qlogq(q);  S += sgn * kA;
    }
    if ((unsigned)bB < (unsigned)NBINS) {
        float q = h[bB], qn = q + sgn * kB;
        h[bB] = qn;  T2 += qlogq(qn) - qlogq(q);  S += sgn * kB;
    }
}

__global__ __launch_bounds__(THREADS, 2)
void entropy_kernel(const float* __restrict__ in, float* __restrict__ out) {
    extern __shared__ float smem[];
    float* tile = smem + IMG * HSTRIDE;

    const int tid   = threadIdx.x;
    const int col   = tid >> 1;                    // column 0..95
    const int par   = tid & 1;                     // bin parity owned
    const int plane = blockIdx.y;
    const int r0    = blockIdx.x * SEG;
    const float* img = in  + (size_t)plane * IMG * IMG;
    float*       o   = out + (size_t)plane * IMG * IMG;

    // ---- tile: rows r0-2..r0+SEG+1, cols -2..97; OOB sentinel -10
    // (bins negative -> rejected == SAME padding's additive identity) ----
    for (int idx = tid; idx < TROWS * TCOLS; idx += THREADS) {
        int r = idx / TCOLS, c = idx % TCOLS;
        int gy = r0 + r - 2, gx = c - 2;
        float v = -10.0f;
        if ((unsigned)gy < (unsigned)IMG && (unsigned)gx < (unsigned)IMG)
            v = img[gy * IMG + gx];
        tile[idx] = v;
    }

    // ---- zero own half of the column histogram (interleaved quads) ----
    float* h  = smem + col * HSTRIDE;
    float4* h4 = (float4*)h;
    #pragma unroll 8
    for (int i = par; i < NBINS / 4; i += 2)
        h4[i] = make_float4(0.f, 0.f, 0.f, 0.f);

    __syncthreads();

    // ---- build initial histogram for y = r0 (own-parity bins only) ----
    float S = 0.f, T2 = 0.f;   // partial over owned bins
    #pragma unroll 1
    for (int wr = 0; wr < 5; wr++) {
        const float* trow = tile + wr * TCOLS + col;
        #pragma unroll
        for (int wc = 0; wc < 5; wc++) {
            float v = trow[wc];
            if (v >= 0.f) {
                Kset ks = kde4(v);
                int bA, bB; float kA, kB;
                if ((ks.i0 & 1) == par) { bA = ks.i0;     kA = ks.k0;  bB = ks.i0 + 2; kB = ks.k2; }
                else                    { bA = ks.i0 - 1; kA = ks.km1; bB = ks.i0 + 1; kB = ks.k1; }
                if ((unsigned)bA < (unsigned)NBINS) h[bA] += kA;
                if ((unsigned)bB < (unsigned)NBINS) h[bB] += kB;
            }
        }
    }

    // ---- initial scan over owned interleaved quads: S, T2 ----
    #pragma unroll 4
    for (int i = par; i < NBINS / 4; i += 2) {
        float4 q = h4[i];
        S  += (q.x + q.y) + (q.z + q.w);
        T2 += qlogq(q.x) + qlogq(q.y) + qlogq(q.z) + qlogq(q.w);
    }

    {
        float St = S  + __shfl_xor_sync(0xffffffffu, S,  1);
        float Tt = T2 + __shfl_xor_sync(0xffffffffu, T2, 1);
        float Sp = St + 1e-10f;
        if (par == 0)
            o[r0 * IMG + col] = __fdividef(St * __logf(Sp) - Tt, Sp);
    }

    // ---- slide down: remove tile row step-1, add tile row step+4 ----
    #pragma unroll 1
    for (int step = 1; step < SEG; step++) {
        const float* rem = tile + (step - 1) * TCOLS + col;
        const float* add = tile + (step + 4) * TCOLS + col;

        #pragma unroll
        for (int wc = 0; wc < 5; wc++) {
            float v = rem[wc];
            if (v >= 0.f) { Kset ks = kde4(v); update2(h, ks, par, -1.f, S, T2); }
        }
        #pragma unroll
        for (int wc = 0; wc < 5; wc++) {
            float v = add[wc];
            if (v >= 0.f) { Kset ks = kde4(v); update2(h, ks, par, +1.f, S, T2); }
        }

        float St = S  + __shfl_xor_sync(0xffffffffu, S,  1);
        float Tt = T2 + __shfl_xor_sync(0xffffffffu, T2, 1);
        float Sp = St + 1e-10f;
        if (par == 0)
            o[(r0 + step) * IMG + col] = __fdividef(St * __logf(Sp) - Tt, Sp);
    }
}

extern "C" void kernel_launch(void* const* d_in, const int* in_sizes, int n_in,
                              void* d_out, int out_size) {
    const float* x = (const float*)d_in[0];
    float* out = (float*)d_out;

    cudaFuncSetAttribute(entropy_kernel,
                         cudaFuncAttributeMaxDynamicSharedMemorySize, SMEM_BYTES);

    int planes = in_sizes[0] / (IMG * IMG);   // 24
    dim3 grid(NSEG, planes);                  // (12, 24) = 288 CTAs
    entropy_kernel<<<grid, THREADS, SMEM_BYTES>>>(x, out);
}